// round 11
// baseline (speedup 1.0000x reference)
#include <cuda_runtime.h>
#include <cstdint>

#define B_ 256
#define T_ 512
#define D_ 128
#define H_ 128
#define G_ 384          // 3H, gate order z|r|h
#define BT_ (B_*T_)

__device__ float g_xp[(size_t)BT_ * G_];   // 201 MB scratch
__device__ float g_h0[(size_t)BT_ * H_];   // 67 MB scratch

typedef unsigned long long u64;

static __device__ __forceinline__ u64 pack2(float a, float b) {
    u64 r; asm("mov.b64 %0, {%1, %2};" : "=l"(r) : "f"(a), "f"(b)); return r;
}
static __device__ __forceinline__ void unpack2(u64 v, float &a, float &b) {
    asm("mov.b64 {%0, %1}, %2;" : "=f"(a), "=f"(b) : "l"(v));
}
static __device__ __forceinline__ u64 fma2(u64 a, u64 b, u64 c) {
    u64 d; asm("fma.rn.f32x2 %0, %1, %2, %3;" : "=l"(d) : "l"(a), "l"(b), "l"(c)); return d;
}
// MUFU tanh (sm_75+ PTX, not arch-'a' gated)
static __device__ __forceinline__ float tanh_mufu(float x) {
    float r; asm("tanh.approx.f32 %0, %1;" : "=f"(r) : "f"(x)); return r;
}
static __device__ __forceinline__ float sig_mufu(float x) {
    return fmaf(0.5f, tanh_mufu(0.5f * x), 0.5f);
}

// ---------------------------------------------------------------------------
// Projection, scan-style layout: 256 threads; thread (u, kg) with
// kg = lane>>4 (k-half), u = warp*16 + lane&15 owns gate-triple columns
// {u, u+128, u+256} over its 64-k half (96 u64 weight regs). Per row:
// 16 broadcast LDS.128 -> 96 FFMA2 -> 3 shfl.xor(16) -> lane<16 STG.
// No smem partials; barrier only at the 8-row x-buffer swap.
// z/r recurrent biases are folded into the projection bias here.
// ---------------------------------------------------------------------------
__global__ __launch_bounds__(256, 1)
void proj_kernel(const float* __restrict__ x, const float* __restrict__ W,
                 const float* __restrict__ bin, const float* __restrict__ brec,
                 float* __restrict__ out, int rows_per_block)
{
    __shared__ __align__(16) float x_sm[2][8][D_];
    const int tid  = threadIdx.x;
    const int lane = tid & 31;
    const int kg   = lane >> 4;
    const int u    = (tid >> 5) * 16 + (lane & 15);
    const int kb   = kg * 64;

    u64 w[3][32];
#pragma unroll
    for (int i = 0; i < 32; i++)
#pragma unroll
        for (int c = 0; c < 3; c++)
            w[c][i] = pack2(W[(kb + 2*i) * G_ + u + c*128],
                            W[(kb + 2*i + 1) * G_ + u + c*128]);
    // fold recurrent z/r bias into projection bias (h-gate bias stays in scan)
    const float b0 = bin[u]       + brec[u];
    const float b1 = bin[u + 128] + brec[u + 128];
    const float b2 = bin[u + 256];

    const int row0 = blockIdx.x * rows_per_block;
    ((float4*)&x_sm[0][0][0])[tid] = ((const float4*)(x + (size_t)row0 * D_))[tid];
    __syncthreads();

    const int iters = rows_per_block / 8;
    int buf = 0;
    for (int it = 0; it < iters; it++) {
        const int rbase = row0 + it * 8;
        float4 nx;
        const bool pre = (it + 1 < iters);
        if (pre)
            nx = ((const float4*)(x + (size_t)(rbase + 8) * D_))[tid];

#pragma unroll
        for (int r = 0; r < 8; r++) {
            u64 a0 = 0, a1 = 0, a2 = 0;
            const float* xs = &x_sm[buf][r][kb];
#pragma unroll
            for (int i2 = 0; i2 < 16; i2++) {
                ulonglong2 hv = *(const ulonglong2*)&xs[4*i2];
                a0 = fma2(hv.x, w[0][2*i2],     a0);
                a0 = fma2(hv.y, w[0][2*i2 + 1], a0);
                a1 = fma2(hv.x, w[1][2*i2],     a1);
                a1 = fma2(hv.y, w[1][2*i2 + 1], a1);
                a2 = fma2(hv.x, w[2][2*i2],     a2);
                a2 = fma2(hv.y, w[2][2*i2 + 1], a2);
            }
            float pa, pb, pc, pd, pe, pf;
            unpack2(a0, pa, pb);
            unpack2(a1, pc, pd);
            unpack2(a2, pe, pf);
            float s0 = pa + pb, s1 = pc + pd, s2 = pe + pf;
            s0 += __shfl_xor_sync(0xffffffffu, s0, 16);
            s1 += __shfl_xor_sync(0xffffffffu, s1, 16);
            s2 += __shfl_xor_sync(0xffffffffu, s2, 16);
            if (lane < 16) {
                float* o = out + (size_t)(rbase + r) * G_;
                o[u]       = s0 + b0;
                o[u + 128] = s1 + b1;
                o[u + 256] = s2 + b2;
            }
        }
        if (pre)
            ((float4*)&x_sm[buf ^ 1][0][0])[tid] = nx;
        __syncthreads();
        buf ^= 1;
    }
}

// ---------------------------------------------------------------------------
// GRU scan (R10, 409us): 256 threads, 2 rows/CTA; z/r biases pre-folded in xp.
// ---------------------------------------------------------------------------
__global__ __launch_bounds__(256, 1)
void gru_scan(const float* __restrict__ U, const float* __restrict__ brec,
              const float* __restrict__ xp, float* __restrict__ out)
{
    __shared__ __align__(16) float h_sm[2][2][2][68];  // [buf][row][kg][pad]
    const int tid  = threadIdx.x;
    const int lane = tid & 31;
    const int kg   = lane >> 4;
    const int u    = (tid >> 5) * 16 + (lane & 15);
    const int kb   = kg * 64;

    u64 w[3][32];
#pragma unroll
    for (int i = 0; i < 32; i++)
#pragma unroll
        for (int c = 0; c < 3; c++)
            w[c][i] = pack2(U[(kb + 2*i) * G_ + u + c*128],
                            U[(kb + 2*i + 1) * G_ + u + c*128]);
    const float bh = brec[u + 256];   // h-gate recurrent bias (inside r*(...))

    const int row = kg;
    const int b0  = blockIdx.x * 2;
    const float* exr = xp + (size_t)(b0 + row) * T_ * G_;
    float* eo = out + (size_t)(b0 + row) * T_ * H_;

    float xz  = exr[u];
    float xr_ = exr[u + 128];
    float xh  = exr[u + 256];
    float hp  = 0.0f;

    if (tid < 128) {
        h_sm[0][0][tid >> 6][tid & 63] = 0.0f;
        h_sm[0][1][tid >> 6][tid & 63] = 0.0f;
    }
    __syncthreads();

    for (int t = 0; t < T_; t++) {
        const int buf = t & 1;
        float nxz = 0.f, nxr = 0.f, nxh = 0.f;
        if (t + 1 < T_) {
            const float* xn = exr + (size_t)(t + 1) * G_;
            nxz = xn[u]; nxr = xn[u + 128]; nxh = xn[u + 256];
        }

        u64 a00 = 0, a01 = 0, a02 = 0, a10 = 0, a11 = 0, a12 = 0;
        const float* h0p = &h_sm[buf][0][kg][0];
        const float* h1p = &h_sm[buf][1][kg][0];
#pragma unroll
        for (int i2 = 0; i2 < 16; i2++) {
            ulonglong2 h0 = *(const ulonglong2*)&h0p[4*i2];
            ulonglong2 h1 = *(const ulonglong2*)&h1p[4*i2];
            a00 = fma2(h0.x, w[0][2*i2], a00);
            a00 = fma2(h0.y, w[0][2*i2 + 1], a00);
            a01 = fma2(h0.x, w[1][2*i2], a01);
            a01 = fma2(h0.y, w[1][2*i2 + 1], a01);
            a02 = fma2(h0.x, w[2][2*i2], a02);
            a02 = fma2(h0.y, w[2][2*i2 + 1], a02);
            a10 = fma2(h1.x, w[0][2*i2], a10);
            a10 = fma2(h1.y, w[0][2*i2 + 1], a10);
            a11 = fma2(h1.x, w[1][2*i2], a11);
            a11 = fma2(h1.y, w[1][2*i2 + 1], a11);
            a12 = fma2(h1.x, w[2][2*i2], a12);
            a12 = fma2(h1.y, w[2][2*i2 + 1], a12);
        }
        float s[2][3];
        { float a, b;
          unpack2(a00, a, b); s[0][0] = a + b;
          unpack2(a01, a, b); s[0][1] = a + b;
          unpack2(a02, a, b); s[0][2] = a + b;
          unpack2(a10, a, b); s[1][0] = a + b;
          unpack2(a11, a, b); s[1][1] = a + b;
          unpack2(a12, a, b); s[1][2] = a + b; }

        float own0 = kg ? s[1][0] : s[0][0];
        float own1 = kg ? s[1][1] : s[0][1];
        float own2 = kg ? s[1][2] : s[0][2];
        float oth0 = kg ? s[0][0] : s[1][0];
        float oth1 = kg ? s[0][1] : s[1][1];
        float oth2 = kg ? s[0][2] : s[1][2];
        float rz = own0 + __shfl_xor_sync(0xffffffffu, oth0, 16);
        float rr = own1 + __shfl_xor_sync(0xffffffffu, oth1, 16);
        float rh = own2 + __shfl_xor_sync(0xffffffffu, oth2, 16) + bh;

        float z  = sig_mufu(xz + rz);
        float rg = sig_mufu(xr_ + rr);
        float hh = tanh_mufu(xh + rg * rh);
        float hn = hh + z * (hp - hh);
        hp = hn;
        h_sm[buf ^ 1][row][u >> 6][u & 63] = hn;
        eo[(size_t)t * H_ + u] = hn;
        xz = nxz; xr_ = nxr; xh = nxh;
        __syncthreads();
    }
}

// ---------------------------------------------------------------------------
extern "C" void kernel_launch(void* const* d_in, const int* in_sizes, int n_in,
                              void* d_out, int out_size)
{
    const float* x  = (const float*)d_in[0];
    const float* W0 = (const float*)d_in[1];
    const float* U0 = (const float*)d_in[2];
    const float* b0 = (const float*)d_in[3];
    const float* W1 = (const float*)d_in[4];
    const float* U1 = (const float*)d_in[5];
    const float* b1 = (const float*)d_in[6];
    float* out = (float*)d_out;

    float *xp, *h0;
    cudaGetSymbolAddress((void**)&xp, g_xp);
    cudaGetSymbolAddress((void**)&h0, g_h0);

    const int PROJ_GRID = 1024;
    const int rpb = BT_ / PROJ_GRID;   // 128 rows per block

    // layer 0
    proj_kernel<<<PROJ_GRID, 256>>>(x, W0, b0, b0 + G_, xp, rpb);
    gru_scan<<<B_ / 2, 256>>>(U0, b0 + G_, xp, h0);
    // layer 1
    proj_kernel<<<PROJ_GRID, 256>>>(h0, W1, b1, b1 + G_, xp, rpb);
    gru_scan<<<B_ / 2, 256>>>(U1, b1 + G_, xp, out);
}

// round 12
// speedup vs baseline: 1.5204x; 1.5204x over previous
#include <cuda_runtime.h>
#include <cstdint>

#define B_ 256
#define T_ 512
#define D_ 128
#define H_ 128
#define G_ 384          // 3H, gate order z|r|h
#define BT_ (B_*T_)

__device__ float g_xp[(size_t)BT_ * G_];   // 201 MB scratch
__device__ float g_h0[(size_t)BT_ * H_];   // 67 MB scratch

typedef unsigned long long u64;

static __device__ __forceinline__ u64 pack2(float a, float b) {
    u64 r; asm("mov.b64 %0, {%1, %2};" : "=l"(r) : "f"(a), "f"(b)); return r;
}
static __device__ __forceinline__ void unpack2(u64 v, float &a, float &b) {
    asm("mov.b64 {%0, %1}, %2;" : "=f"(a), "=f"(b) : "l"(v));
}
static __device__ __forceinline__ u64 fma2(u64 a, u64 b, u64 c) {
    u64 d; asm("fma.rn.f32x2 %0, %1, %2, %3;" : "=l"(d) : "l"(a), "l"(b), "l"(c)); return d;
}
// MUFU tanh (sm_75+ PTX, not arch-'a' gated)
static __device__ __forceinline__ float tanh_mufu(float x) {
    float r; asm("tanh.approx.f32 %0, %1;" : "=f"(r) : "f"(x)); return r;
}
static __device__ __forceinline__ float sig_mufu(float x) {
    return fmaf(0.5f, tanh_mufu(0.5f * x), 0.5f);
}

// ---------------------------------------------------------------------------
// Projection, scan-style layout (R11, measured ~291us/layer): 256 threads;
// thread (u, kg) with kg = lane>>4 (k-half), u = warp*16 + lane&15 owns
// gate-triple columns {u, u+128, u+256} over its 64-k half (96 u64 weight
// regs). Per row: 16 broadcast LDS.128 -> 96 FFMA2 -> 3 shfl.xor(16) ->
// lane<16 STG. No smem partials; barrier only at the 8-row x-buffer swap.
// Bias = input-projection bias only (recurrent bias handled in the scan).
// ---------------------------------------------------------------------------
__global__ __launch_bounds__(256, 1)
void proj_kernel(const float* __restrict__ x, const float* __restrict__ W,
                 const float* __restrict__ bin, float* __restrict__ out,
                 int rows_per_block)
{
    __shared__ __align__(16) float x_sm[2][8][D_];
    const int tid  = threadIdx.x;
    const int lane = tid & 31;
    const int kg   = lane >> 4;
    const int u    = (tid >> 5) * 16 + (lane & 15);
    const int kb   = kg * 64;

    u64 w[3][32];
#pragma unroll
    for (int i = 0; i < 32; i++)
#pragma unroll
        for (int c = 0; c < 3; c++)
            w[c][i] = pack2(W[(kb + 2*i) * G_ + u + c*128],
                            W[(kb + 2*i + 1) * G_ + u + c*128]);
    const float b0 = bin[u];
    const float b1 = bin[u + 128];
    const float b2 = bin[u + 256];

    const int row0 = blockIdx.x * rows_per_block;
    ((float4*)&x_sm[0][0][0])[tid] = ((const float4*)(x + (size_t)row0 * D_))[tid];
    __syncthreads();

    const int iters = rows_per_block / 8;
    int buf = 0;
    for (int it = 0; it < iters; it++) {
        const int rbase = row0 + it * 8;
        float4 nx;
        const bool pre = (it + 1 < iters);
        if (pre)
            nx = ((const float4*)(x + (size_t)(rbase + 8) * D_))[tid];

#pragma unroll
        for (int r = 0; r < 8; r++) {
            u64 a0 = 0, a1 = 0, a2 = 0;
            const float* xs = &x_sm[buf][r][kb];
#pragma unroll
            for (int i2 = 0; i2 < 16; i2++) {
                ulonglong2 hv = *(const ulonglong2*)&xs[4*i2];
                a0 = fma2(hv.x, w[0][2*i2],     a0);
                a0 = fma2(hv.y, w[0][2*i2 + 1], a0);
                a1 = fma2(hv.x, w[1][2*i2],     a1);
                a1 = fma2(hv.y, w[1][2*i2 + 1], a1);
                a2 = fma2(hv.x, w[2][2*i2],     a2);
                a2 = fma2(hv.y, w[2][2*i2 + 1], a2);
            }
            float pa, pb, pc, pd, pe, pf;
            unpack2(a0, pa, pb);
            unpack2(a1, pc, pd);
            unpack2(a2, pe, pf);
            float s0 = pa + pb, s1 = pc + pd, s2 = pe + pf;
            s0 += __shfl_xor_sync(0xffffffffu, s0, 16);
            s1 += __shfl_xor_sync(0xffffffffu, s1, 16);
            s2 += __shfl_xor_sync(0xffffffffu, s2, 16);
            if (lane < 16) {
                float* o = out + (size_t)(rbase + r) * G_;
                o[u]       = s0 + b0;
                o[u + 128] = s1 + b1;
                o[u + 256] = s2 + b2;
            }
        }
        if (pre)
            ((float4*)&x_sm[buf ^ 1][0][0])[tid] = nx;
        __syncthreads();
        buf ^= 1;
    }
}

// ---------------------------------------------------------------------------
// GRU scan — VERBATIM R10 version (measured 409us): 256 threads, 2 rows/CTA.
// Thread (u,kg): kg = lane>>4 (k-half), u = warp*16 + lane&15. Owns gate
// columns {u, u+128, u+256} over its k-half for BOTH rows; single fused
// accumulator chain per (row,col); k-reduce = 3 shfl.xor(16); gate chain via
// MUFU tanh.approx. h double-buffered, ONE barrier per step.
// ---------------------------------------------------------------------------
__global__ __launch_bounds__(256, 1)
void gru_scan(const float* __restrict__ U, const float* __restrict__ brec,
              const float* __restrict__ xp, float* __restrict__ out)
{
    __shared__ __align__(16) float h_sm[2][2][2][68];  // [buf][row][kg][pad]
    const int tid  = threadIdx.x;
    const int lane = tid & 31;
    const int kg   = lane >> 4;
    const int u    = (tid >> 5) * 16 + (lane & 15);
    const int kb   = kg * 64;

    u64 w[3][32];
#pragma unroll
    for (int i = 0; i < 32; i++)
#pragma unroll
        for (int c = 0; c < 3; c++)
            w[c][i] = pack2(U[(kb + 2*i) * G_ + u + c*128],
                            U[(kb + 2*i + 1) * G_ + u + c*128]);
    const float bz = brec[u], br_ = brec[u + 128], bh = brec[u + 256];

    const int row = kg;
    const int b0  = blockIdx.x * 2;
    const float* exr = xp + (size_t)(b0 + row) * T_ * G_;
    float* eo = out + (size_t)(b0 + row) * T_ * H_;

    float xz  = exr[u];
    float xr_ = exr[u + 128];
    float xh  = exr[u + 256];
    float hp  = 0.0f;

    if (tid < 128) {
        h_sm[0][0][tid >> 6][tid & 63] = 0.0f;
        h_sm[0][1][tid >> 6][tid & 63] = 0.0f;
    }
    __syncthreads();

    for (int t = 0; t < T_; t++) {
        const int buf = t & 1;
        float nxz = 0.f, nxr = 0.f, nxh = 0.f;
        if (t + 1 < T_) {
            const float* xn = exr + (size_t)(t + 1) * G_;
            nxz = xn[u]; nxr = xn[u + 128]; nxh = xn[u + 256];
        }

        // --- matvec: both rows x 3 gate columns, fused accumulator chains ---
        u64 a00 = 0, a01 = 0, a02 = 0, a10 = 0, a11 = 0, a12 = 0;
        const float* h0p = &h_sm[buf][0][kg][0];
        const float* h1p = &h_sm[buf][1][kg][0];
#pragma unroll
        for (int i2 = 0; i2 < 16; i2++) {
            ulonglong2 h0 = *(const ulonglong2*)&h0p[4*i2];
            ulonglong2 h1 = *(const ulonglong2*)&h1p[4*i2];
            a00 = fma2(h0.x, w[0][2*i2], a00);
            a00 = fma2(h0.y, w[0][2*i2 + 1], a00);
            a01 = fma2(h0.x, w[1][2*i2], a01);
            a01 = fma2(h0.y, w[1][2*i2 + 1], a01);
            a02 = fma2(h0.x, w[2][2*i2], a02);
            a02 = fma2(h0.y, w[2][2*i2 + 1], a02);
            a10 = fma2(h1.x, w[0][2*i2], a10);
            a10 = fma2(h1.y, w[0][2*i2 + 1], a10);
            a11 = fma2(h1.x, w[1][2*i2], a11);
            a11 = fma2(h1.y, w[1][2*i2 + 1], a11);
            a12 = fma2(h1.x, w[2][2*i2], a12);
            a12 = fma2(h1.y, w[2][2*i2 + 1], a12);
        }
        float s[2][3];
        { float a, b;
          unpack2(a00, a, b); s[0][0] = a + b;
          unpack2(a01, a, b); s[0][1] = a + b;
          unpack2(a02, a, b); s[0][2] = a + b;
          unpack2(a10, a, b); s[1][0] = a + b;
          unpack2(a11, a, b); s[1][1] = a + b;
          unpack2(a12, a, b); s[1][2] = a + b; }

        // k-reduction across kg (lane bit 4)
        float own0 = kg ? s[1][0] : s[0][0];
        float own1 = kg ? s[1][1] : s[0][1];
        float own2 = kg ? s[1][2] : s[0][2];
        float oth0 = kg ? s[0][0] : s[1][0];
        float oth1 = kg ? s[0][1] : s[1][1];
        float oth2 = kg ? s[0][2] : s[1][2];
        float rz = own0 + __shfl_xor_sync(0xffffffffu, oth0, 16) + bz;
        float rr = own1 + __shfl_xor_sync(0xffffffffu, oth1, 16) + br_;
        float rh = own2 + __shfl_xor_sync(0xffffffffu, oth2, 16) + bh;

        // --- gate chain (MUFU tanh) ---
        float z  = sig_mufu(xz + rz);
        float rg = sig_mufu(xr_ + rr);
        float hh = tanh_mufu(xh + rg * rh);
        float hn = hh + z * (hp - hh);
        hp = hn;
        h_sm[buf ^ 1][row][u >> 6][u & 63] = hn;
        eo[(size_t)t * H_ + u] = hn;
        xz = nxz; xr_ = nxr; xh = nxh;
        __syncthreads();
    }
}

// ---------------------------------------------------------------------------
extern "C" void kernel_launch(void* const* d_in, const int* in_sizes, int n_in,
                              void* d_out, int out_size)
{
    const float* x  = (const float*)d_in[0];
    const float* W0 = (const float*)d_in[1];
    const float* U0 = (const float*)d_in[2];
    const float* b0 = (const float*)d_in[3];
    const float* W1 = (const float*)d_in[4];
    const float* U1 = (const float*)d_in[5];
    const float* b1 = (const float*)d_in[6];
    float* out = (float*)d_out;

    float *xp, *h0;
    cudaGetSymbolAddress((void**)&xp, g_xp);
    cudaGetSymbolAddress((void**)&h0, g_h0);

    const int PROJ_GRID = 1024;
    const int rpb = BT_ / PROJ_GRID;   // 128 rows per block

    // layer 0
    proj_kernel<<<PROJ_GRID, 256>>>(x, W0, b0, xp, rpb);
    gru_scan<<<B_ / 2, 256>>>(U0, b0 + G_, xp, h0);
    // layer 1
    proj_kernel<<<PROJ_GRID, 256>>>(h0, W1, b1, xp, rpb);
    gru_scan<<<B_ / 2, 256>>>(U1, b1 + G_, xp, out);
}